// round 14
// baseline (speedup 1.0000x reference)
#include <cuda_runtime.h>
#include <cuda_bf16.h>

// Shapes
#define Bn 16
#define Tn 128
#define In 8
#define Dn 128
#define NT 2048           // Tn * Bn tokens, t = r*16 + b

// Output packing (fp32 concat of the reference tuple)
#define EMB_SZ   (NT*Dn)        // 262144
#define PAD_OFF  (EMB_SZ)       // padding_mask (B,T)
#define SEQ_OFF  (PAD_OFF+2048) // sequence_mask (T,B,1)
#define GLB_OFF  (SEQ_OFF+2048) // global_mask (T)
#define OUT_ALL  (GLB_OFF+128)  // 266368

// ---------------- scratch (device globals: allocation-free) ----------------
__device__ __align__(16) float g_M1[Dn*Dn];   // Wq @ Wk^T
__device__ __align__(16) float g_M2[Dn*Dn];   // Wv @ W_out
__device__ __align__(16) float g_Qp[NT*Dn];   // LN(diag-x) @ M1 / sqrt(D)
__device__ __align__(16) float g_Y [NT*Dn];   // softmax-weighted LN-combined rows
__device__ float g_seq[NT];     // seq[r,b] as 0/1
__device__ int   g_mask_mode;   // 0=byte, 1=int32, 2=float32

// ---------------- helpers ----------------
// tanh-form gelu with HW tanh.approx.f32: ONE MUFU op
__device__ __forceinline__ float gelu_f(float x) {
    float u = 0.7978845608028654f * fmaf(0.044715f * x, x * x, x);
    float th;
    asm("tanh.approx.f32 %0, %1;" : "=f"(th) : "f"(u));
    float hx = 0.5f * x;
    return fmaf(hx, th, hx);
}

__device__ __forceinline__ float mask_at(const void* m, int idx, int mode) {
    if (mode == 0) return ((const unsigned char*)m)[idx] ? 1.0f : 0.0f;
    if (mode == 1) return ((const int*)m)[idx] ? 1.0f : 0.0f;
    return (((const float*)m)[idx] != 0.0f) ? 1.0f : 0.0f;
}

// ---------------- K1: probe + M1 = Wq @ Wk^T ; M2 = Wv @ W_out ----------------
__global__ void k_precompute(const float* __restrict__ Wq, const float* __restrict__ Wk,
                             const float* __restrict__ Wv, const float* __restrict__ Wo,
                             const void* __restrict__ maskp) {
    extern __shared__ float sm[];
    int i = blockIdx.x, j = threadIdx.x;
    if (blockIdx.y == 0) {
        if (i == 0 && j == 0) {
            unsigned int w = *(const unsigned int*)maskp;
            g_mask_mode = (w == 1u) ? 1 : ((w == 0x3F800000u) ? 2 : 0);
        }
        float* wks  = sm;               // [128][129] padded
        float* rowq = sm + 128 * 129;
        for (int idx = j; idx < 128 * 128; idx += 128) {
            int rr = idx >> 7, cc = idx & 127;
            wks[rr * 129 + cc] = Wk[idx];
        }
        rowq[j] = Wq[i * 128 + j];
        __syncthreads();
        float acc = 0.f;
#pragma unroll 8
        for (int k = 0; k < 128; k++) acc += rowq[k] * wks[j * 129 + k];
        g_M1[i * 128 + j] = acc;
    } else {
        float* rowv = sm;
        rowv[j] = Wv[i * 128 + j];
        __syncthreads();
        float acc = 0.f;
#pragma unroll 8
        for (int k = 0; k < 128; k++) acc += rowv[k] * Wo[k * 128 + j];
        g_M2[i * 128 + j] = acc;
    }
}

// ---------------- K2: diag tokens -> LN -> Qp, + mask outputs ----------------
__global__ void __launch_bounds__(128) k_pre(
    const float* __restrict__ vectors, const void* __restrict__ maskp,
    const float* __restrict__ We, const float* __restrict__ be,
    const float* __restrict__ g1, const float* __restrict__ b1,
    float* __restrict__ out, int out_size) {
    __shared__ float vs[64];
    __shared__ float mval[8];
    __shared__ float xds[8 * 128];
    int r = blockIdx.x >> 1, bb = (blockIdx.x & 1) << 3;
    int tid = threadIdx.x, lane = tid & 31, w = tid >> 5;
    int mode = g_mask_mode;

    if (tid < 64) {
        int tt = tid >> 3, i = tid & 7;
        vs[tid] = vectors[(((((bb + tt) * Tn + r) * Tn) + r) << 3) + i];
    }
    if (tid < 8) mval[tid] = mask_at(maskp, ((bb + tid) * Tn + r) * Tn + r, mode);
    float wcol[8];
#pragma unroll
    for (int i = 0; i < 8; i++) wcol[i] = We[i * 128 + tid];
    float bed = be[tid];
    __syncthreads();

#pragma unroll
    for (int tt = 0; tt < 8; tt++) {
        float e = bed;
#pragma unroll
        for (int i = 0; i < 8; i++) e = fmaf(vs[tt * 8 + i], wcol[i], e);
        xds[tt * 128 + tid] = gelu_f(e) * mval[tt];
    }
    __syncthreads();

    {
        float g1r0 = g1[lane], g1r1 = g1[lane + 32], g1r2 = g1[lane + 64], g1r3 = g1[lane + 96];
        float b1r0 = b1[lane], b1r1 = b1[lane + 32], b1r2 = b1[lane + 64], b1r3 = b1[lane + 96];
        for (int tt = w; tt < 8; tt += 4) {
            float* row = xds + tt * 128;
            float v0 = row[lane], v1 = row[lane + 32], v2 = row[lane + 64], v3 = row[lane + 96];
            float s = v0 + v1 + v2 + v3;
            float q = v0 * v0 + v1 * v1 + v2 * v2 + v3 * v3;
#pragma unroll
            for (int o = 16; o > 0; o >>= 1) {
                s += __shfl_xor_sync(0xffffffffu, s, o);
                q += __shfl_xor_sync(0xffffffffu, q, o);
            }
            float mu  = s * (1.0f / 128.0f);
            float var = q * (1.0f / 128.0f) - mu * mu;
            float rstd = rsqrtf(var + 1e-5f);
            row[lane]      = (v0 - mu) * rstd * g1r0 + b1r0;
            row[lane + 32] = (v1 - mu) * rstd * g1r1 + b1r1;
            row[lane + 64] = (v2 - mu) * rstd * g1r2 + b1r2;
            row[lane + 96] = (v3 - mu) * rstd * g1r3 + b1r3;
        }
    }
    __syncthreads();

    {
        int dg = tid & 31, tg = tid >> 5;
        const float4* M14 = (const float4*)g_M1;
        const float* yA = xds + (tg * 2) * 128;
        const float* yB = xds + (tg * 2 + 1) * 128;
        float a0 = 0, a1 = 0, a2 = 0, a3 = 0, c0 = 0, c1 = 0, c2 = 0, c3 = 0;
#pragma unroll 8
        for (int e = 0; e < 128; e++) {
            float4 m = M14[e * 32 + dg];
            float ya = yA[e], yb = yB[e];
            a0 = fmaf(ya, m.x, a0); a1 = fmaf(ya, m.y, a1);
            a2 = fmaf(ya, m.z, a2); a3 = fmaf(ya, m.w, a3);
            c0 = fmaf(yb, m.x, c0); c1 = fmaf(yb, m.y, c1);
            c2 = fmaf(yb, m.z, c2); c3 = fmaf(yb, m.w, c3);
        }
        const float sc = 0.08838834764831845f;
        int tokA = (r << 4) + bb + tg * 2;
        float4* Qp4 = (float4*)g_Qp;
        Qp4[tokA * 32 + dg]       = make_float4(a0 * sc, a1 * sc, a2 * sc, a3 * sc);
        Qp4[(tokA + 1) * 32 + dg] = make_float4(c0 * sc, c1 * sc, c2 * sc, c3 * sc);
    }

    if (tid < 8) {
        float sval = mval[tid];
        int t = (r << 4) + bb + tid;
        g_seq[t] = sval;
        if (out_size >= SEQ_OFF) out[PAD_OFF + (bb + tid) * Tn + r] = (sval > 0.f) ? 0.f : 1.f;
        if (out_size >= GLB_OFF) out[SEQ_OFF + t] = sval;
    }
    if (tid == 0 && bb == 0 && out_size >= OUT_ALL) out[GLB_OFF + r] = 1.0f;
}

// ---------------- K3: fused embed+stats attention, LN folded, 256 threads ----------------
// Phases A+B fused: thread pair (c, hh) produces row c's 64 x-values AND its
// s/q/dot stats in registers. xs stride 136 (S=8 mod 32): float4 writes at
// j = 2g+hh tile all 32 banks per 8-lane phase -> conflict-free.
#define XSTR   136
#define XS_F   (128*XSTR)
// smem floats: xs | WeS 1024 (aliased by ypart 256 in phase C) | beS 128 | qg 128 | As 128
#define K3_SMEM ((XS_F + 1024 + 128 + 128 + 128) * 4)
__global__ void __launch_bounds__(256, 3) k_attn(
    const float* __restrict__ vectors, const void* __restrict__ maskp,
    const float* __restrict__ We, const float* __restrict__ be,
    const float* __restrict__ g1, const float* __restrict__ b1) {
    extern __shared__ float sm[];
    float* xs    = sm;
    float* WeS   = xs + XS_F;       // [8][128], phase A only
    float* ypart = WeS;             // alias: phase C partials [2][128]
    float* beS   = WeS + 1024;
    float* qg    = beS + 128;       // g1 * qp
    float* As    = qg + 128;        // p_c * rstd_c
    __shared__ float sred[16];

    int t = blockIdx.x, r = t >> 4, b = t & 15, tid = threadIdx.x;
    int lane = tid & 31, w = tid >> 5;
    int d = tid & 127, h = tid >> 7;
    int mode = g_mask_mode;

    // stage We [8][128] and be
    ((float4*)WeS)[tid] = ((const float4*)We)[tid];
    if (tid < 32) ((float4*)beS)[tid] = ((const float4*)be)[tid];

    float qp  = g_Qp[t * 128 + d];
    float g1v = g1[d], b1v = b1[d];
    float qgv = g1v * qp;
    if (h == 0) qg[d] = qgv;
    { // S1 = sum(g1*qp), C0 = sum(b1*qp)
        float s1p = (h == 0) ? qgv : 0.f;
        float c0p = (h == 0) ? b1v * qp : 0.f;
#pragma unroll
        for (int o = 16; o > 0; o >>= 1) {
            s1p += __shfl_xor_sync(0xffffffffu, s1p, o);
            c0p += __shfl_xor_sync(0xffffffffu, c0p, o);
        }
        if (lane == 0) { sred[w] = s1p; sred[8 + w] = c0p; }
    }
    float mr = mask_at(maskp, (b * Tn + r) * Tn + d, mode);
    int cnt = __syncthreads_count(mr > 0.f) >> 1;   // barrier: fences WeS/beS/qg/sred
    float S1 = ((sred[0] + sred[1]) + (sred[2] + sred[3]))
             + ((sred[4] + sred[5]) + (sred[6] + sred[7]));
    float C0 = ((sred[8] + sred[9]) + (sred[10] + sred[11]))
             + ((sred[12] + sred[13]) + (sred[14] + sred[15]));

    // ---- Fused A+B: thread (c, hh) computes x[c][d] for its 64 d's + stats ----
    int c = tid >> 1, hh = tid & 1;
    bool act = (c < cnt) || (c == r);
    float s = 0.f, q = 0.f, dot = 0.f;
    if (act) {
        const float4* vr = (const float4*)(vectors + ((size_t)(b * Tn + r) * Tn + c) * In);
        float4 va = __ldg(vr), vb = __ldg(vr + 1);
        const float4* We4 = (const float4*)WeS;
        const float4* be4 = (const float4*)beS;
        const float4* qg4 = (const float4*)qg;
        float4* xrow = (float4*)(xs + c * XSTR);
        float s0=0,s1=0, q0=0,q1=0, t0a=0,t1a=0;
#pragma unroll 2
        for (int g = 0; g < 16; g++) {
            int j = 2 * g + hh;
            float4 e = be4[j];
            {
                float4 w0 = We4[j], w1 = We4[32 + j], w2 = We4[64 + j], w3 = We4[96 + j];
                e.x = fmaf(va.x, w0.x, e.x); e.y = fmaf(va.x, w0.y, e.y);
                e.z = fmaf(va.x, w0.z, e.z); e.w = fmaf(va.x, w0.w, e.w);
                e.x = fmaf(va.y, w1.x, e.x); e.y = fmaf(va.y, w1.y, e.y);
                e.z = fmaf(va.y, w1.z, e.z); e.w = fmaf(va.y, w1.w, e.w);
                e.x = fmaf(va.z, w2.x, e.x); e.y = fmaf(va.z, w2.y, e.y);
                e.z = fmaf(va.z, w2.z, e.z); e.w = fmaf(va.z, w2.w, e.w);
                e.x = fmaf(va.w, w3.x, e.x); e.y = fmaf(va.w, w3.y, e.y);
                e.z = fmaf(va.w, w3.z, e.z); e.w = fmaf(va.w, w3.w, e.w);
            }
            {
                float4 w4 = We4[128 + j], w5 = We4[160 + j], w6 = We4[192 + j], w7 = We4[224 + j];
                e.x = fmaf(vb.x, w4.x, e.x); e.y = fmaf(vb.x, w4.y, e.y);
                e.z = fmaf(vb.x, w4.z, e.z); e.w = fmaf(vb.x, w4.w, e.w);
                e.x = fmaf(vb.y, w5.x, e.x); e.y = fmaf(vb.y, w5.y, e.y);
                e.z = fmaf(vb.y, w5.z, e.z); e.w = fmaf(vb.y, w5.w, e.w);
                e.x = fmaf(vb.z, w6.x, e.x); e.y = fmaf(vb.z, w6.y, e.y);
                e.z = fmaf(vb.z, w6.z, e.z); e.w = fmaf(vb.z, w6.w, e.w);
                e.x = fmaf(vb.w, w7.x, e.x); e.y = fmaf(vb.w, w7.y, e.y);
                e.z = fmaf(vb.w, w7.z, e.z); e.w = fmaf(vb.w, w7.w, e.w);
            }
            float4 x4;
            x4.x = gelu_f(e.x); x4.y = gelu_f(e.y);
            x4.z = gelu_f(e.z); x4.w = gelu_f(e.w);
            float4 qv = qg4[j];
            s0 += x4.x + x4.z;                 s1 += x4.y + x4.w;
            q0 = fmaf(x4.x, x4.x, q0);         q1 = fmaf(x4.y, x4.y, q1);
            q0 = fmaf(x4.z, x4.z, q0);         q1 = fmaf(x4.w, x4.w, q1);
            t0a = fmaf(x4.x, qv.x, t0a);       t1a = fmaf(x4.y, qv.y, t1a);
            t0a = fmaf(x4.z, qv.z, t0a);       t1a = fmaf(x4.w, qv.w, t1a);
            xrow[j] = x4;
        }
        s = s0 + s1; q = q0 + q1; dot = t0a + t1a;
    }
    s   += __shfl_xor_sync(0xffffffffu, s, 1);
    q   += __shfl_xor_sync(0xffffffffu, q, 1);
    dot += __shfl_xor_sync(0xffffffffu, dot, 1);
    __syncthreads();   // xs rows visible to all; sred safe for reuse

    float mu   = s * (1.0f / 128.0f);
    float var  = q * (1.0f / 128.0f) - mu * mu;
    float rstd = rsqrtf(var + 1e-5f);
    float logit = (c < cnt || c == r) ? fmaf(rstd, dot - mu * S1, C0) : -1e9f;

    // softmax over 128 rows
    float mx = logit;
#pragma unroll
    for (int o = 16; o > 0; o >>= 1) mx = fmaxf(mx, __shfl_xor_sync(0xffffffffu, mx, o));
    if (lane == 0) sred[w] = mx;
    __syncthreads();
    mx = fmaxf(fmaxf(fmaxf(sred[0], sred[1]), fmaxf(sred[2], sred[3])),
               fmaxf(fmaxf(sred[4], sred[5]), fmaxf(sred[6], sred[7])));

    float p = __expf(logit - mx);
    float A = p * rstd;
    if (hh == 0) As[c] = A;
    {
        float ps = (hh == 0) ? p : 0.f;
        float bp = (hh == 0) ? A * mu : 0.f;
#pragma unroll
        for (int o = 16; o > 0; o >>= 1) {
            ps += __shfl_xor_sync(0xffffffffu, ps, o);
            bp += __shfl_xor_sync(0xffffffffu, bp, o);
        }
        if (lane == 0) { sred[w] = ps; sred[8 + w] = bp; }
    }
    __syncthreads();
    float psum = ((sred[0] + sred[1]) + (sred[2] + sred[3]))
               + ((sred[4] + sred[5]) + (sred[6] + sred[7]));
    float beta = ((sred[8] + sred[9]) + (sred[10] + sred[11]))
               + ((sred[12] + sred[13]) + (sred[14] + sred[15]));
    float inv  = __frcp_rn(psum);

    // Phase C: half h sums rows of its parity; WeS dead -> ypart alias safe
    {
        float y0 = 0.f, y1 = 0.f;
        int cc = h;
#pragma unroll 4
        for (; cc + 2 < cnt; cc += 4) {
            y0 = fmaf(As[cc],     xs[cc * XSTR + d],       y0);
            y1 = fmaf(As[cc + 2], xs[(cc + 2) * XSTR + d], y1);
        }
        for (; cc < cnt; cc += 2) y0 = fmaf(As[cc], xs[cc * XSTR + d], y0);
        ypart[h * 128 + d] = y0 + y1;
    }
    __syncthreads();
    if (h == 0) {
        float y = ypart[d] + ypart[128 + d];
        g_Y[t * 128 + d] = fmaf(g1v, (y - beta) * inv, b1v);
    }
}

// ---------------- K4: Emb = Y@Wv, H = gelu(Y@M2+bo), out = LN(H+Emb)*seq ----------------
// grid 1024 (2 tokens/block), block 256: half = matrix, dg = d-quad, es = e-chunk(32)
__global__ void __launch_bounds__(256) k_out(
    const float* __restrict__ Wv, const float* __restrict__ bo,
    const float* __restrict__ g2, const float* __restrict__ b2,
    float* __restrict__ out, int out_size) {
    __shared__ float ys[256];
    __shared__ float zpf[2048];     // [half][es][tok2][128 d]
    __shared__ float zs[2 * 129];
    int tid = threadIdx.x, t0 = blockIdx.x * 2;
    int half = tid >> 7, id = tid & 127, dg = id & 31, es = id >> 5;

    if (tid < 64) ((float4*)ys)[tid] = ((const float4*)(g_Y + t0 * 128))[tid];
    __syncthreads();

    const float4* W4 = (const float4*)(half ? g_M2 : Wv);
    float4 a0 = {0,0,0,0}, a1 = {0,0,0,0};
    int e0 = es * 32;
#pragma unroll 4
    for (int e = e0; e < e0 + 32; e++) {
        float4 m = W4[e * 32 + dg];
        float y0 = ys[e], y1 = ys[128 + e];
        a0.x = fmaf(y0, m.x, a0.x); a0.y = fmaf(y0, m.y, a0.y);
        a0.z = fmaf(y0, m.z, a0.z); a0.w = fmaf(y0, m.w, a0.w);
        a1.x = fmaf(y1, m.x, a1.x); a1.y = fmaf(y1, m.y, a1.y);
        a1.z = fmaf(y1, m.z, a1.z); a1.w = fmaf(y1, m.w, a1.w);
    }
    {
        float4* zp4 = (float4*)zpf;
        int base = ((half * 4 + es) * 2) * 32 + dg;
        zp4[base]      = a0;
        zp4[base + 32] = a1;
    }
    __syncthreads();

    // reduce across es, combine E/H, gelu+residual -> zs (one (tok,d) per thread)
    {
        int tok = tid >> 7, dd = tid & 127;
        float E = 0.f, H = 0.f;
#pragma unroll
        for (int e2 = 0; e2 < 4; e2++) {
            E += zpf[((0 * 4 + e2) * 2 + tok) * 128 + dd];
            H += zpf[((1 * 4 + e2) * 2 + tok) * 128 + dd];
        }
        zs[tok * 129 + dd] = gelu_f(H + bo[dd]) + E;
    }
    __syncthreads();

    // LN: warp per token (warps 0-1)
    if (out_size >= EMB_SZ && tid < 64) {
        int w = tid >> 5, lane = tid & 31;
        float* row = zs + w * 129;
        float v0 = row[lane], v1 = row[lane + 32], v2 = row[lane + 64], v3 = row[lane + 96];
        float s = v0 + v1 + v2 + v3;
        float q = v0 * v0 + v1 * v1 + v2 * v2 + v3 * v3;
#pragma unroll
        for (int o = 16; o > 0; o >>= 1) {
            s += __shfl_xor_sync(0xffffffffu, s, o);
            q += __shfl_xor_sync(0xffffffffu, q, o);
        }
        float mu  = s * (1.0f / 128.0f);
        float var = q * (1.0f / 128.0f) - mu * mu;
        float rstd = rsqrtf(var + 1e-5f);
        float sf = g_seq[t0 + w];
        int ob = (t0 + w) * 128;
        out[ob + lane]      = ((v0 - mu) * rstd * g2[lane]      + b2[lane])      * sf;
        out[ob + lane + 32] = ((v1 - mu) * rstd * g2[lane + 32] + b2[lane + 32]) * sf;
        out[ob + lane + 64] = ((v2 - mu) * rstd * g2[lane + 64] + b2[lane + 64]) * sf;
        out[ob + lane + 96] = ((v3 - mu) * rstd * g2[lane + 96] + b2[lane + 96]) * sf;
    }
}

// ---------------- launch ----------------
extern "C" void kernel_launch(void* const* d_in, const int* in_sizes, int n_in,
                              void* d_out, int out_size) {
    const float* vectors = (const float*)d_in[0];
    const void*  maskp   = d_in[1];
    const float* We = (const float*)d_in[2];
    const float* be = (const float*)d_in[3];
    const float* g1 = (const float*)d_in[4];
    const float* b1 = (const float*)d_in[5];
    const float* Wq = (const float*)d_in[6];
    const float* Wk = (const float*)d_in[7];
    const float* Wv = (const float*)d_in[8];
    const float* Wo = (const float*)d_in[9];
    const float* bo = (const float*)d_in[10];
    const float* g2 = (const float*)d_in[11];
    const float* b2 = (const float*)d_in[12];
    float* out = (float*)d_out;

    int pre_smem = (128 * 129 + 128) * 4;
    cudaFuncSetAttribute(k_precompute, cudaFuncAttributeMaxDynamicSharedMemorySize, pre_smem);
    cudaFuncSetAttribute(k_attn,       cudaFuncAttributeMaxDynamicSharedMemorySize, K3_SMEM);

    k_precompute<<<dim3(128, 2), 128, pre_smem>>>(Wq, Wk, Wv, Wo, maskp);
    k_pre<<<256, 128>>>(vectors, maskp, We, be, g1, b1, out, out_size);
    k_attn<<<NT, 256, K3_SMEM>>>(vectors, maskp, We, be, g1, b1);
    k_out<<<1024, 256>>>(Wv, bo, g2, b2, out, out_size);
}

// round 15
// speedup vs baseline: 1.0460x; 1.0460x over previous
#include <cuda_runtime.h>
#include <cuda_bf16.h>
#include <cuda_fp16.h>

// Shapes
#define Bn 16
#define Tn 128
#define In 8
#define Dn 128
#define NT 2048           // Tn * Bn tokens, t = r*16 + b

// Output packing (fp32 concat of the reference tuple)
#define EMB_SZ   (NT*Dn)        // 262144
#define PAD_OFF  (EMB_SZ)       // padding_mask (B,T)
#define SEQ_OFF  (PAD_OFF+2048) // sequence_mask (T,B,1)
#define GLB_OFF  (SEQ_OFF+2048) // global_mask (T)
#define OUT_ALL  (GLB_OFF+128)  // 266368

// ---------------- scratch (device globals: allocation-free) ----------------
__device__ __align__(16) float g_M1[Dn*Dn];   // Wq @ Wk^T
__device__ __align__(16) float g_M2[Dn*Dn];   // Wv @ W_out
__device__ __align__(16) float g_Qp[NT*Dn];   // LN(diag-x) @ M1 / sqrt(D)
__device__ __align__(16) float g_Y [NT*Dn];   // softmax-weighted LN-combined rows
__device__ float g_seq[NT];     // seq[r,b] as 0/1
__device__ int   g_mask_mode;   // 0=byte, 1=int32, 2=float32

// ---------------- helpers ----------------
// tanh-form gelu with HW tanh.approx.f32: ONE MUFU op
__device__ __forceinline__ float gelu_f(float x) {
    float u = 0.7978845608028654f * fmaf(0.044715f * x, x * x, x);
    float th;
    asm("tanh.approx.f32 %0, %1;" : "=f"(th) : "f"(u));
    float hx = 0.5f * x;
    return fmaf(hx, th, hx);
}

__device__ __forceinline__ float mask_at(const void* m, int idx, int mode) {
    if (mode == 0) return ((const unsigned char*)m)[idx] ? 1.0f : 0.0f;
    if (mode == 1) return ((const int*)m)[idx] ? 1.0f : 0.0f;
    return (((const float*)m)[idx] != 0.0f) ? 1.0f : 0.0f;
}

// ---------------- K1: probe + M1 = Wq @ Wk^T ; M2 = Wv @ W_out ----------------
__global__ void k_precompute(const float* __restrict__ Wq, const float* __restrict__ Wk,
                             const float* __restrict__ Wv, const float* __restrict__ Wo,
                             const void* __restrict__ maskp) {
    extern __shared__ float sm[];
    int i = blockIdx.x, j = threadIdx.x;
    if (blockIdx.y == 0) {
        if (i == 0 && j == 0) {
            unsigned int w = *(const unsigned int*)maskp;
            g_mask_mode = (w == 1u) ? 1 : ((w == 0x3F800000u) ? 2 : 0);
        }
        float* wks  = sm;               // [128][129] padded
        float* rowq = sm + 128 * 129;
        for (int idx = j; idx < 128 * 128; idx += 128) {
            int rr = idx >> 7, cc = idx & 127;
            wks[rr * 129 + cc] = Wk[idx];
        }
        rowq[j] = Wq[i * 128 + j];
        __syncthreads();
        float acc = 0.f;
#pragma unroll 8
        for (int k = 0; k < 128; k++) acc += rowq[k] * wks[j * 129 + k];
        g_M1[i * 128 + j] = acc;
    } else {
        float* rowv = sm;
        rowv[j] = Wv[i * 128 + j];
        __syncthreads();
        float acc = 0.f;
#pragma unroll 8
        for (int k = 0; k < 128; k++) acc += rowv[k] * Wo[k * 128 + j];
        g_M2[i * 128 + j] = acc;
    }
}

// ---------------- K2: diag tokens -> LN -> Qp, + mask outputs ----------------
__global__ void __launch_bounds__(128) k_pre(
    const float* __restrict__ vectors, const void* __restrict__ maskp,
    const float* __restrict__ We, const float* __restrict__ be,
    const float* __restrict__ g1, const float* __restrict__ b1,
    float* __restrict__ out, int out_size) {
    __shared__ float vs[64];
    __shared__ float mval[8];
    __shared__ float xds[8 * 128];
    int r = blockIdx.x >> 1, bb = (blockIdx.x & 1) << 3;
    int tid = threadIdx.x, lane = tid & 31, w = tid >> 5;
    int mode = g_mask_mode;

    if (tid < 64) {
        int tt = tid >> 3, i = tid & 7;
        vs[tid] = vectors[(((((bb + tt) * Tn + r) * Tn) + r) << 3) + i];
    }
    if (tid < 8) mval[tid] = mask_at(maskp, ((bb + tid) * Tn + r) * Tn + r, mode);
    float wcol[8];
#pragma unroll
    for (int i = 0; i < 8; i++) wcol[i] = We[i * 128 + tid];
    float bed = be[tid];
    __syncthreads();

#pragma unroll
    for (int tt = 0; tt < 8; tt++) {
        float e = bed;
#pragma unroll
        for (int i = 0; i < 8; i++) e = fmaf(vs[tt * 8 + i], wcol[i], e);
        xds[tt * 128 + tid] = gelu_f(e) * mval[tt];
    }
    __syncthreads();

    {
        float g1r0 = g1[lane], g1r1 = g1[lane + 32], g1r2 = g1[lane + 64], g1r3 = g1[lane + 96];
        float b1r0 = b1[lane], b1r1 = b1[lane + 32], b1r2 = b1[lane + 64], b1r3 = b1[lane + 96];
        for (int tt = w; tt < 8; tt += 4) {
            float* row = xds + tt * 128;
            float v0 = row[lane], v1 = row[lane + 32], v2 = row[lane + 64], v3 = row[lane + 96];
            float s = v0 + v1 + v2 + v3;
            float q = v0 * v0 + v1 * v1 + v2 * v2 + v3 * v3;
#pragma unroll
            for (int o = 16; o > 0; o >>= 1) {
                s += __shfl_xor_sync(0xffffffffu, s, o);
                q += __shfl_xor_sync(0xffffffffu, q, o);
            }
            float mu  = s * (1.0f / 128.0f);
            float var = q * (1.0f / 128.0f) - mu * mu;
            float rstd = rsqrtf(var + 1e-5f);
            row[lane]      = (v0 - mu) * rstd * g1r0 + b1r0;
            row[lane + 32] = (v1 - mu) * rstd * g1r1 + b1r1;
            row[lane + 64] = (v2 - mu) * rstd * g1r2 + b1r2;
            row[lane + 96] = (v3 - mu) * rstd * g1r3 + b1r3;
        }
    }
    __syncthreads();

    {
        int dg = tid & 31, tg = tid >> 5;
        const float4* M14 = (const float4*)g_M1;
        const float* yA = xds + (tg * 2) * 128;
        const float* yB = xds + (tg * 2 + 1) * 128;
        float a0 = 0, a1 = 0, a2 = 0, a3 = 0, c0 = 0, c1 = 0, c2 = 0, c3 = 0;
#pragma unroll 8
        for (int e = 0; e < 128; e++) {
            float4 m = M14[e * 32 + dg];
            float ya = yA[e], yb = yB[e];
            a0 = fmaf(ya, m.x, a0); a1 = fmaf(ya, m.y, a1);
            a2 = fmaf(ya, m.z, a2); a3 = fmaf(ya, m.w, a3);
            c0 = fmaf(yb, m.x, c0); c1 = fmaf(yb, m.y, c1);
            c2 = fmaf(yb, m.z, c2); c3 = fmaf(yb, m.w, c3);
        }
        const float sc = 0.08838834764831845f;
        int tokA = (r << 4) + bb + tg * 2;
        float4* Qp4 = (float4*)g_Qp;
        Qp4[tokA * 32 + dg]       = make_float4(a0 * sc, a1 * sc, a2 * sc, a3 * sc);
        Qp4[(tokA + 1) * 32 + dg] = make_float4(c0 * sc, c1 * sc, c2 * sc, c3 * sc);
    }

    if (tid < 8) {
        float sval = mval[tid];
        int t = (r << 4) + bb + tid;
        g_seq[t] = sval;
        if (out_size >= SEQ_OFF) out[PAD_OFF + (bb + tid) * Tn + r] = (sval > 0.f) ? 0.f : 1.f;
        if (out_size >= GLB_OFF) out[SEQ_OFF + t] = sval;
    }
    if (tid == 0 && bb == 0 && out_size >= OUT_ALL) out[GLB_OFF + r] = 1.0f;
}

// ---------------- K3: fused embed+stats attention, fp16 x tile, 4 CTAs/SM ----------------
// Stats (s, q, dot) computed in FP32 registers during production -> logits exact.
// Only phase C's weighted sum reads the fp16 tile (err ~1e-4 after averaging).
#define XSTR   136      // stride in HALVES; row base = 272 B (8B-aligned)
// smem: floats [WeS 1024 | beS 128 | qg 128 | As 128] then half xs[128*136]
#define K3_FHDR (1024 + 128 + 128 + 128)
#define K3_SMEM (K3_FHDR * 4 + 128 * XSTR * 2)
__global__ void __launch_bounds__(256, 4) k_attn(
    const float* __restrict__ vectors, const void* __restrict__ maskp,
    const float* __restrict__ We, const float* __restrict__ be,
    const float* __restrict__ g1, const float* __restrict__ b1) {
    extern __shared__ float sm[];
    float* WeS   = sm;              // [8][128], fused-phase only
    float* ypart = WeS;             // alias: phase C partials [2][128]
    float* beS   = WeS + 1024;
    float* qg    = beS + 128;       // g1 * qp
    float* As    = qg + 128;        // p_c * rstd_c
    __half* xs   = (__half*)(sm + K3_FHDR);
    __shared__ float sred[16];

    int t = blockIdx.x, r = t >> 4, b = t & 15, tid = threadIdx.x;
    int lane = tid & 31, w = tid >> 5;
    int d = tid & 127, h = tid >> 7;
    int mode = g_mask_mode;

    // stage We [8][128] and be
    ((float4*)WeS)[tid] = ((const float4*)We)[tid];
    if (tid < 32) ((float4*)beS)[tid] = ((const float4*)be)[tid];

    float qp  = g_Qp[t * 128 + d];
    float g1v = g1[d], b1v = b1[d];
    float qgv = g1v * qp;
    if (h == 0) qg[d] = qgv;
    { // S1 = sum(g1*qp), C0 = sum(b1*qp)
        float s1p = (h == 0) ? qgv : 0.f;
        float c0p = (h == 0) ? b1v * qp : 0.f;
#pragma unroll
        for (int o = 16; o > 0; o >>= 1) {
            s1p += __shfl_xor_sync(0xffffffffu, s1p, o);
            c0p += __shfl_xor_sync(0xffffffffu, c0p, o);
        }
        if (lane == 0) { sred[w] = s1p; sred[8 + w] = c0p; }
    }
    float mr = mask_at(maskp, (b * Tn + r) * Tn + d, mode);
    int cnt = __syncthreads_count(mr > 0.f) >> 1;   // barrier: fences WeS/beS/qg/sred
    float S1 = ((sred[0] + sred[1]) + (sred[2] + sred[3]))
             + ((sred[4] + sred[5]) + (sred[6] + sred[7]));
    float C0 = ((sred[8] + sred[9]) + (sred[10] + sred[11]))
             + ((sred[12] + sred[13]) + (sred[14] + sred[15]));

    // ---- Fused A+B: thread (c, hh) computes x[c][d] for its 64 d's + fp32 stats ----
    int c = tid >> 1, hh = tid & 1;
    bool act = (c < cnt) || (c == r);
    float s = 0.f, q = 0.f, dot = 0.f;
    if (act) {
        const float4* vr = (const float4*)(vectors + ((size_t)(b * Tn + r) * Tn + c) * In);
        float4 va = __ldg(vr), vb = __ldg(vr + 1);
        const float4* We4 = (const float4*)WeS;
        const float4* be4 = (const float4*)beS;
        const float4* qg4 = (const float4*)qg;
        uint2* xrow = (uint2*)(xs + c * XSTR);
        float s0=0,s1=0, q0=0,q1=0, t0a=0,t1a=0;
#pragma unroll 2
        for (int g = 0; g < 16; g++) {
            int j = 2 * g + hh;
            float4 e = be4[j];
            {
                float4 w0 = We4[j], w1 = We4[32 + j], w2 = We4[64 + j], w3 = We4[96 + j];
                e.x = fmaf(va.x, w0.x, e.x); e.y = fmaf(va.x, w0.y, e.y);
                e.z = fmaf(va.x, w0.z, e.z); e.w = fmaf(va.x, w0.w, e.w);
                e.x = fmaf(va.y, w1.x, e.x); e.y = fmaf(va.y, w1.y, e.y);
                e.z = fmaf(va.y, w1.z, e.z); e.w = fmaf(va.y, w1.w, e.w);
                e.x = fmaf(va.z, w2.x, e.x); e.y = fmaf(va.z, w2.y, e.y);
                e.z = fmaf(va.z, w2.z, e.z); e.w = fmaf(va.z, w2.w, e.w);
                e.x = fmaf(va.w, w3.x, e.x); e.y = fmaf(va.w, w3.y, e.y);
                e.z = fmaf(va.w, w3.z, e.z); e.w = fmaf(va.w, w3.w, e.w);
            }
            {
                float4 w4 = We4[128 + j], w5 = We4[160 + j], w6 = We4[192 + j], w7 = We4[224 + j];
                e.x = fmaf(vb.x, w4.x, e.x); e.y = fmaf(vb.x, w4.y, e.y);
                e.z = fmaf(vb.x, w4.z, e.z); e.w = fmaf(vb.x, w4.w, e.w);
                e.x = fmaf(vb.y, w5.x, e.x); e.y = fmaf(vb.y, w5.y, e.y);
                e.z = fmaf(vb.y, w5.z, e.z); e.w = fmaf(vb.y, w5.w, e.w);
                e.x = fmaf(vb.z, w6.x, e.x); e.y = fmaf(vb.z, w6.y, e.y);
                e.z = fmaf(vb.z, w6.z, e.z); e.w = fmaf(vb.z, w6.w, e.w);
                e.x = fmaf(vb.w, w7.x, e.x); e.y = fmaf(vb.w, w7.y, e.y);
                e.z = fmaf(vb.w, w7.z, e.z); e.w = fmaf(vb.w, w7.w, e.w);
            }
            float4 x4;
            x4.x = gelu_f(e.x); x4.y = gelu_f(e.y);
            x4.z = gelu_f(e.z); x4.w = gelu_f(e.w);
            float4 qv = qg4[j];
            s0 += x4.x + x4.z;                 s1 += x4.y + x4.w;
            q0 = fmaf(x4.x, x4.x, q0);         q1 = fmaf(x4.y, x4.y, q1);
            q0 = fmaf(x4.z, x4.z, q0);         q1 = fmaf(x4.w, x4.w, q1);
            t0a = fmaf(x4.x, qv.x, t0a);       t1a = fmaf(x4.y, qv.y, t1a);
            t0a = fmaf(x4.z, qv.z, t0a);       t1a = fmaf(x4.w, qv.w, t1a);
            __half2 h01 = __floats2half2_rn(x4.x, x4.y);
            __half2 h23 = __floats2half2_rn(x4.z, x4.w);
            uint2 u;
            u.x = *(unsigned int*)&h01;
            u.y = *(unsigned int*)&h23;
            xrow[j] = u;
        }
        s = s0 + s1; q = q0 + q1; dot = t0a + t1a;
    }
    s   += __shfl_xor_sync(0xffffffffu, s, 1);
    q   += __shfl_xor_sync(0xffffffffu, q, 1);
    dot += __shfl_xor_sync(0xffffffffu, dot, 1);
    __syncthreads();   // xs rows visible; sred reusable

    float mu   = s * (1.0f / 128.0f);
    float var  = q * (1.0f / 128.0f) - mu * mu;
    float rstd = rsqrtf(var + 1e-5f);
    float logit = (c < cnt || c == r) ? fmaf(rstd, dot - mu * S1, C0) : -1e9f;

    // softmax over 128 rows
    float mx = logit;
#pragma unroll
    for (int o = 16; o > 0; o >>= 1) mx = fmaxf(mx, __shfl_xor_sync(0xffffffffu, mx, o));
    if (lane == 0) sred[w] = mx;
    __syncthreads();
    mx = fmaxf(fmaxf(fmaxf(sred[0], sred[1]), fmaxf(sred[2], sred[3])),
               fmaxf(fmaxf(sred[4], sred[5]), fmaxf(sred[6], sred[7])));

    float p = __expf(logit - mx);
    float A = p * rstd;
    if (hh == 0) As[c] = A;
    {
        float ps = (hh == 0) ? p : 0.f;
        float bp = (hh == 0) ? A * mu : 0.f;
#pragma unroll
        for (int o = 16; o > 0; o >>= 1) {
            ps += __shfl_xor_sync(0xffffffffu, ps, o);
            bp += __shfl_xor_sync(0xffffffffu, bp, o);
        }
        if (lane == 0) { sred[w] = ps; sred[8 + w] = bp; }
    }
    __syncthreads();
    float psum = ((sred[0] + sred[1]) + (sred[2] + sred[3]))
               + ((sred[4] + sred[5]) + (sred[6] + sred[7]));
    float beta = ((sred[8] + sred[9]) + (sred[10] + sred[11]))
               + ((sred[12] + sred[13]) + (sred[14] + sred[15]));
    float inv  = __frcp_rn(psum);

    // Phase C: half h sums rows of its parity (fp16 loads, fp32 accum);
    // WeS dead -> ypart alias safe
    {
        float y0 = 0.f, y1 = 0.f;
        int cc = h;
#pragma unroll 4
        for (; cc + 2 < cnt; cc += 4) {
            y0 = fmaf(As[cc],     __half2float(xs[cc * XSTR + d]),       y0);
            y1 = fmaf(As[cc + 2], __half2float(xs[(cc + 2) * XSTR + d]), y1);
        }
        for (; cc < cnt; cc += 2) y0 = fmaf(As[cc], __half2float(xs[cc * XSTR + d]), y0);
        ypart[h * 128 + d] = y0 + y1;
    }
    __syncthreads();
    if (h == 0) {
        float y = ypart[d] + ypart[128 + d];
        g_Y[t * 128 + d] = fmaf(g1v, (y - beta) * inv, b1v);
    }
}

// ---------------- K4: Emb = Y@Wv, H = gelu(Y@M2+bo), out = LN(H+Emb)*seq ----------------
// grid 512 (4 tokens/block), block 256 (measured-optimal R8/R12 config)
__global__ void __launch_bounds__(256) k_out(
    const float* __restrict__ Wv, const float* __restrict__ bo,
    const float* __restrict__ g2, const float* __restrict__ b2,
    float* __restrict__ out, int out_size) {
    __shared__ float ys[512];
    __shared__ float zpf[4096];     // [half][es][tok][128 d]
    __shared__ float zs[4 * 129];
    int tid = threadIdx.x, t0 = blockIdx.x * 4;
    int half = tid >> 7, id = tid & 127, dg = id & 31, es = id >> 5;

    if (tid < 128) ((float4*)ys)[tid] = ((const float4*)(g_Y + t0 * 128))[tid];
    __syncthreads();

    const float4* W4 = (const float4*)(half ? g_M2 : Wv);
    float4 a0 = {0,0,0,0}, a1 = {0,0,0,0}, a2 = {0,0,0,0}, a3 = {0,0,0,0};
    int e0 = es * 32;
#pragma unroll 4
    for (int e = e0; e < e0 + 32; e++) {
        float4 m = W4[e * 32 + dg];
        float y0 = ys[e], y1 = ys[128 + e], y2 = ys[256 + e], y3 = ys[384 + e];
        a0.x = fmaf(y0, m.x, a0.x); a0.y = fmaf(y0, m.y, a0.y);
        a0.z = fmaf(y0, m.z, a0.z); a0.w = fmaf(y0, m.w, a0.w);
        a1.x = fmaf(y1, m.x, a1.x); a1.y = fmaf(y1, m.y, a1.y);
        a1.z = fmaf(y1, m.z, a1.z); a1.w = fmaf(y1, m.w, a1.w);
        a2.x = fmaf(y2, m.x, a2.x); a2.y = fmaf(y2, m.y, a2.y);
        a2.z = fmaf(y2, m.z, a2.z); a2.w = fmaf(y2, m.w, a2.w);
        a3.x = fmaf(y3, m.x, a3.x); a3.y = fmaf(y3, m.y, a3.y);
        a3.z = fmaf(y3, m.z, a3.z); a3.w = fmaf(y3, m.w, a3.w);
    }
    {
        float4* zp4 = (float4*)zpf;
        int base = ((half * 4 + es) * 4) * 32 + dg;
        zp4[base]      = a0;
        zp4[base + 32] = a1;
        zp4[base + 64] = a2;
        zp4[base + 96] = a3;
    }
    __syncthreads();

    // reduce across es, combine E/H, gelu+residual -> zs
#pragma unroll
    for (int pp = 0; pp < 2; pp++) {
        int p = tid + pp * 256;          // (tok, d) pair, 512 total
        int tok = p >> 7, dd = p & 127;
        float E = 0.f, H = 0.f;
#pragma unroll
        for (int e2 = 0; e2 < 4; e2++) {
            E += zpf[((0 * 4 + e2) * 4 + tok) * 128 + dd];
            H += zpf[((1 * 4 + e2) * 4 + tok) * 128 + dd];
        }
        zs[tok * 129 + dd] = gelu_f(H + bo[dd]) + E;
    }
    __syncthreads();

    // LN: warp per token (warps 0-3)
    if (out_size >= EMB_SZ && tid < 128) {
        int w = tid >> 5, lane = tid & 31;
        float* row = zs + w * 129;
        float v0 = row[lane], v1 = row[lane + 32], v2 = row[lane + 64], v3 = row[lane + 96];
        float s = v0 + v1 + v2 + v3;
        float q = v0 * v0 + v1 * v1 + v2 * v2 + v3 * v3;
#pragma unroll
        for (int o = 16; o > 0; o >>= 1) {
            s += __shfl_xor_sync(0xffffffffu, s, o);
            q += __shfl_xor_sync(0xffffffffu, q, o);
        }
        float mu  = s * (1.0f / 128.0f);
        float var = q * (1.0f / 128.0f) - mu * mu;
        float rstd = rsqrtf(var + 1e-5f);
        float sf = g_seq[t0 + w];
        int ob = (t0 + w) * 128;
        out[ob + lane]      = ((v0 - mu) * rstd * g2[lane]      + b2[lane])      * sf;
        out[ob + lane + 32] = ((v1 - mu) * rstd * g2[lane + 32] + b2[lane + 32]) * sf;
        out[ob + lane + 64] = ((v2 - mu) * rstd * g2[lane + 64] + b2[lane + 64]) * sf;
        out[ob + lane + 96] = ((v3 - mu) * rstd * g2[lane + 96] + b2[lane + 96]) * sf;
    }
}

// ---------------- launch ----------------
extern "C" void kernel_launch(void* const* d_in, const int* in_sizes, int n_in,
                              void* d_out, int out_size) {
    const float* vectors = (const float*)d_in[0];
    const void*  maskp   = d_in[1];
    const float* We = (const float*)d_in[2];
    const float* be = (const float*)d_in[3];
    const float* g1 = (const float*)d_in[4];
    const float* b1 = (const float*)d_in[5];
    const float* Wq = (const float*)d_in[6];
    const float* Wk = (const float*)d_in[7];
    const float* Wv = (const float*)d_in[8];
    const float* Wo = (const float*)d_in[9];
    const float* bo = (const float*)d_in[10];
    const float* g2 = (const float*)d_in[11];
    const float* b2 = (const float*)d_in[12];
    float* out = (float*)d_out;

    int pre_smem = (128 * 129 + 128) * 4;
    cudaFuncSetAttribute(k_precompute, cudaFuncAttributeMaxDynamicSharedMemorySize, pre_smem);
    cudaFuncSetAttribute(k_attn,       cudaFuncAttributeMaxDynamicSharedMemorySize, K3_SMEM);

    k_precompute<<<dim3(128, 2), 128, pre_smem>>>(Wq, Wk, Wv, Wo, maskp);
    k_pre<<<256, 128>>>(vectors, maskp, We, be, g1, b1, out, out_size);
    k_attn<<<NT, 256, K3_SMEM>>>(vectors, maskp, We, be, g1, b1);
    k_out<<<512, 256>>>(Wv, bo, g2, b2, out, out_size);
}